// round 15
// baseline (speedup 1.0000x reference)
#include <cuda_runtime.h>
#include <cuda_bf16.h>
#include <math.h>
#include <stdint.h>

// ---------------------------------------------------------------------------
// Problem constants
// ---------------------------------------------------------------------------
namespace {
constexpr int T_  = 4;
constexpr int N_  = 512;
constexpr int C_  = 8;
constexpr int D_  = 128;
constexpr int DM_ = 128;
constexpr int K_  = 16;
constexpr int M_  = N_ * C_;     // 4096
constexpr int RP  = T_ * M_;     // 16384
constexpr int RN  = RP * K_;     // 262144

constexpr int PK    = 136;             // padded bf16 row stride (272 B)
constexpr int TILEB = 128 * PK * 2;    // 34816 bytes per 128x128 bf16 tile
constexpr int PAW   = 132;             // padded fp32 stride for the 'a' tile
}

extern __shared__ __align__(1024) char dsm[];

// ---------------------------------------------------------------------------
// Scratch (device globals; zero-initialized; no allocation allowed)
// ---------------------------------------------------------------------------
__device__ float          g_zero[128];
__device__ __nv_bfloat16  g_xbf [RP * DM_];
__device__ float          g_q   [RP * DM_];
__device__ float          g_k   [RP * DM_];
__device__ float          g_v   [RP * DM_];
__device__ __nv_bfloat16  g_resb[RP * DM_];
__device__ int            g_knn [RP * K_];
__device__ __nv_bfloat16  g_wimg[7 * 16384];   // bf16 W^T images, [n][k] row-major

// ---------------------------------------------------------------------------
// Warp-level bf16 MMA + ldmatrix (baseline PTX; fine on plain sm_103 target)
// ---------------------------------------------------------------------------
__device__ __forceinline__ uint32_t smem_u32(const void* p) {
    return (uint32_t)__cvta_generic_to_shared(p);
}
__device__ __forceinline__ void mma16816(float* c, const uint32_t* a,
                                         uint32_t b0, uint32_t b1) {
    asm volatile(
        "mma.sync.aligned.m16n8k16.row.col.f32.bf16.bf16.f32 "
        "{%0,%1,%2,%3}, {%4,%5,%6,%7}, {%8,%9}, {%0,%1,%2,%3};"
        : "+f"(c[0]), "+f"(c[1]), "+f"(c[2]), "+f"(c[3])
        : "r"(a[0]), "r"(a[1]), "r"(a[2]), "r"(a[3]), "r"(b0), "r"(b1));
}
__device__ __forceinline__ void ldmx4(uint32_t* r, uint32_t addr) {
    asm volatile("ldmatrix.sync.aligned.m8n8.x4.shared.b16 {%0,%1,%2,%3}, [%4];"
        : "=r"(r[0]), "=r"(r[1]), "=r"(r[2]), "=r"(r[3]) : "r"(addr));
}
__device__ __forceinline__ void ldmx2(uint32_t* r, uint32_t addr) {
    asm volatile("ldmatrix.sync.aligned.m8n8.x2.shared.b16 {%0,%1}, [%2];"
        : "=r"(r[0]), "=r"(r[1]) : "r"(addr));
}

// Warp computes a 32x64 slice of C = A[128xK=128] @ B^T (B stored [n][k]).
// ldmatrix fragment loads; PK=136 keeps every 8-row phase conflict-free.
__device__ __forceinline__ void warp_mma_tile(
    uint32_t sAu, uint32_t sBu, int wm, int wn, int lane, float acc[2][8][4])
{
    const int lr = lane & 7;
    const int g  = lane >> 3;                       // x4 group 0..3
    // A x4: groups -> (r,k0),(r+8,k0),(r,k0+8),(r+8,k0+8)
    const uint32_t aoff =
        (uint32_t)(((wm * 32 + (g & 1) * 8 + lr) * PK + ((g & 2) ? 8 : 0)) * 2);
    // B x2 (lanes 0-15 used): (n..n+7, k0) and (n..n+7, k0+8)
    const uint32_t boff =
        (uint32_t)(((wn * 64 + lr) * PK + ((lane & 8) ? 8 : 0)) * 2);

#pragma unroll
    for (int ks = 0; ks < 8; ++ks) {
        const uint32_t kb = (uint32_t)(ks * 16 * 2);
        uint32_t a0[4], a1[4];
        ldmx4(a0, sAu + aoff + kb);
        ldmx4(a1, sAu + aoff + (uint32_t)(16 * PK * 2) + kb);
#pragma unroll
        for (int nt = 0; nt < 8; ++nt) {
            uint32_t b[2];
            ldmx2(b, sBu + boff + (uint32_t)(nt * 8 * PK * 2) + kb);
            mma16816(acc[0][nt], a0, b[0], b[1]);
            mma16816(acc[1][nt], a1, b[0], b[1]);
        }
    }
}

// ---------------------------------------------------------------------------
// Weight prep: img[b][n][k] = bf16(W_b[k][n])
// ---------------------------------------------------------------------------
struct WP { const float* w[7]; };
__global__ void prep_weights(WP p, __nv_bfloat16* img)
{
    const int b = blockIdx.x;
    const float* W = p.w[b];
    __nv_bfloat16* base = img + b * 16384;
    for (int i = threadIdx.x; i < 16384; i += blockDim.x) {
        int n = i >> 7, k = i & 127;
        base[i] = __float2bfloat16(W[k * 128 + n]);
    }
}

// ---------------------------------------------------------------------------
// Tensor-core GEMM: C[128-row tile][128] = A @ W + bias (fp32 out).
// blockIdx.y selects (Bimg, C) pair -> q/k/v in one launch.
// smem 2048 + 2*TILEB = 71680 -> 2 CTA/SM.
// ---------------------------------------------------------------------------
struct MG {
    const __nv_bfloat16* Abf;
    const __nv_bfloat16* Bimg[3];
    float* C[3];
    const float* bias;
};

__global__ void __launch_bounds__(256, 2) mma_gemm(MG p)
{
    char* smem = dsm;
    float* sbias = (float*)smem;                       // 512 B
    __nv_bfloat16* sA = (__nv_bfloat16*)(smem + 2048);
    __nv_bfloat16* sB = (__nv_bfloat16*)(smem + 2048 + TILEB);

    const int tid = threadIdx.x;
    const long bm = (long)blockIdx.x * 128;
    const __nv_bfloat16* Bimg = p.Bimg[blockIdx.y];
    float* Cout = p.C[blockIdx.y];

    if (tid < 128) sbias[tid] = p.bias[tid];

    for (int i = tid * 8; i < 128 * 128; i += 256 * 8) {
        int n = i >> 7, c8 = i & 127;
        *(uint4*)&sB[n * PK + c8] = *(const uint4*)&Bimg[i];
    }
    for (int it = 0; it < 8; ++it) {
        int el  = it * 256 + tid;
        int row = el >> 4;
        int c8  = (el & 15) * 8;
        *(uint4*)&sA[row * PK + c8] = *(const uint4*)&p.Abf[(bm + row) * 128 + c8];
    }
    __syncthreads();

    const int lane = tid & 31;
    const int wm = tid >> 6;
    const int wn = (tid >> 5) & 1;
    float acc[2][8][4];
#pragma unroll
    for (int mt = 0; mt < 2; ++mt)
#pragma unroll
        for (int nt = 0; nt < 8; ++nt)
#pragma unroll
            for (int c = 0; c < 4; ++c) acc[mt][nt][c] = 0.f;

    warp_mma_tile(smem_u32(sA), smem_u32(sB), wm, wn, lane, acc);

    const int rq = lane >> 2;
    const int qc = (lane & 3) * 2;
#pragma unroll
    for (int mt = 0; mt < 2; ++mt) {
#pragma unroll
        for (int nt = 0; nt < 8; ++nt) {
            int R  = wm * 32 + mt * 16 + rq;
            int Cc = wn * 64 + nt * 8 + qc;
            float bx = sbias[Cc], by = sbias[Cc + 1];
            float2 lo = make_float2(acc[mt][nt][0] + bx, acc[mt][nt][1] + by);
            float2 hi = make_float2(acc[mt][nt][2] + bx, acc[mt][nt][3] + by);
            *(float2*)&Cout[(bm + R) * 128 + Cc]     = lo;
            *(float2*)&Cout[(bm + R + 8) * 128 + Cc] = hi;
        }
    }
}

// ---------------------------------------------------------------------------
// Fully fused: pos-MLP + gamma-MLP + softmax + aggregate (mma.sync).
// CTA = 128 neighbor-rows = 8 points x 16 neighbors. Three MMAs:
//   ph  = relu(rel @ dw1 + db1)           (scalar build, R4)
//   pos = ph @ dw2 + db2                  (MMA0 vs R1=dw2 img) -> bf16 R5
//   a0  = q - k[knn] + pos                (build into R4)
//   h   = relu(a0 @ gw1 + gb1)            (MMA1 vs R2) -> bf16 R1
//   a   = (h @ gw2 + gb2)*scale           (MMA2 vs R3) -> fp32 aW over R3+R4
//   res = sum_k softmax_k(a) * relu(v[knn] + pos)
// smem: hdr 4096 + 5*TILEB = 178176 -> 1 CTA/SM. g_pos never exists in HBM.
// ---------------------------------------------------------------------------
struct GF {
    const float* q; const float* k; const float* v;
    const float* xyz; const int* knn;
    const __nv_bfloat16* Bpos; const __nv_bfloat16* B1img; const __nv_bfloat16* B2img;
    const float* dw1; const float* db1; const float* db2;
    const float* b1; const float* b2;
    __nv_bfloat16* res;
};

__global__ void __launch_bounds__(256, 1) gamma_soft_mma(GF p)
{
    char* smem = dsm;
    int*   sidx = (int*)smem;                          // 512
    float* sb1v = (float*)(smem + 512);                // 512
    float* sb2v = (float*)(smem + 1024);               // 512
    float* sbp  = (float*)(smem + 1536);               // 512 (db2)
    float* srel = (float*)(smem + 2048);               // 1536
    __nv_bfloat16* sR1 = (__nv_bfloat16*)(smem + 4096);             // dw2 img -> H
    __nv_bfloat16* sR2 = (__nv_bfloat16*)(smem + 4096 + TILEB);     // gw1
    __nv_bfloat16* sR3 = (__nv_bfloat16*)(smem + 4096 + 2 * TILEB); // gw2
    __nv_bfloat16* sR4 = (__nv_bfloat16*)(smem + 4096 + 3 * TILEB); // ph -> a0
    __nv_bfloat16* sPos= (__nv_bfloat16*)(smem + 4096 + 4 * TILEB); // pos bf16
    float* aW = (float*)(smem + 4096 + 2 * TILEB);     // overlays R3+R4 (67584B)

    const int tid = threadIdx.x;
    const long bm = (long)blockIdx.x * 128;    // neighbor-row base
    const int tp0 = blockIdx.x * 8;            // first point
    const int t   = tp0 >> 12;

    if (tid < 128) {
        int idx = p.knn[bm + tid];
        sidx[tid] = idx;
        sb1v[tid] = p.b1[tid];
        sb2v[tid] = p.b2[tid];
        sbp[tid]  = p.db2[tid];
        int tm = (int)((bm + tid) >> 4);
        int m  = tm & 4095;
        const float* xz = p.xyz + (long)t * M_ * 3;
        srel[tid * 3 + 0] = xz[m * 3 + 0] - xz[idx * 3 + 0];
        srel[tid * 3 + 1] = xz[m * 3 + 1] - xz[idx * 3 + 1];
        srel[tid * 3 + 2] = xz[m * 3 + 2] - xz[idx * 3 + 2];
    }
    for (int i = tid * 8; i < 128 * 128; i += 256 * 8) {
        int n = i >> 7, c8 = i & 127;
        *(uint4*)&sR1[n * PK + c8] = *(const uint4*)&p.Bpos[i];
        *(uint4*)&sR2[n * PK + c8] = *(const uint4*)&p.B1img[i];
        *(uint4*)&sR3[n * PK + c8] = *(const uint4*)&p.B2img[i];
    }
    __syncthreads();

    // build ph = relu(rel @ dw1 + db1) into R4
    for (int it = 0; it < 8; ++it) {
        int el  = it * 256 + tid;
        int row = el >> 4;
        int c8  = (el & 15) * 8;
        float rx = srel[row * 3 + 0];
        float ry = srel[row * 3 + 1];
        float rz = srel[row * 3 + 2];
        __nv_bfloat16 buf[8];
#pragma unroll
        for (int j = 0; j < 8; ++j) {
            int c = c8 + j;
            float vv = fmaf(rx, p.dw1[c], fmaf(ry, p.dw1[128 + c],
                         fmaf(rz, p.dw1[256 + c], p.db1[c])));
            buf[j] = __float2bfloat16(fmaxf(vv, 0.f));
        }
        *(uint4*)&sR4[row * PK + c8] = *(uint4*)buf;
    }
    __syncthreads();

    const int lane = tid & 31;
    const int wm = tid >> 6;
    const int wn = (tid >> 5) & 1;
    const int rq = lane >> 2;
    const int qc = (lane & 3) * 2;
    const uint32_t uR1 = smem_u32(sR1), uR2 = smem_u32(sR2),
                   uR3 = smem_u32(sR3), uR4 = smem_u32(sR4);

    float acc[2][8][4];
#define ZACC() do {                               \
    _Pragma("unroll") for (int mt = 0; mt < 2; ++mt)   \
    _Pragma("unroll") for (int nt = 0; nt < 8; ++nt)   \
    _Pragma("unroll") for (int c = 0; c < 4; ++c) acc[mt][nt][c] = 0.f; } while (0)

    // MMA0: ph @ dw2 -> pos (bf16) into R5
    ZACC();
    warp_mma_tile(uR4, uR1, wm, wn, lane, acc);
#pragma unroll
    for (int mt = 0; mt < 2; ++mt) {
#pragma unroll
        for (int nt = 0; nt < 8; ++nt) {
            int R  = wm * 32 + mt * 16 + rq;
            int Cc = wn * 64 + nt * 8 + qc;
            float bx = sbp[Cc], by = sbp[Cc + 1];
            __nv_bfloat16 p0[2], p1[2];
            p0[0] = __float2bfloat16(acc[mt][nt][0] + bx);
            p0[1] = __float2bfloat16(acc[mt][nt][1] + by);
            p1[0] = __float2bfloat16(acc[mt][nt][2] + bx);
            p1[1] = __float2bfloat16(acc[mt][nt][3] + by);
            *(uint32_t*)&sPos[R * PK + Cc]       = *(uint32_t*)p0;
            *(uint32_t*)&sPos[(R + 8) * PK + Cc] = *(uint32_t*)p1;
        }
    }
    __syncthreads();   // all warps done reading R4 (ph) + pos complete

    // build a0 = q - k_gather + pos into R4
    for (int it = 0; it < 8; ++it) {
        int el  = it * 256 + tid;
        int row = el >> 4;
        int c8  = (el & 15) * 8;
        int tm  = tp0 + (row >> 4);
        const float* qp = &p.q[(long)tm * 128 + c8];
        const float* kp = &p.k[(((long)t << 12) + sidx[row]) * 128 + c8];
        __nv_bfloat16 pb[8];
        *(uint4*)pb = *(uint4*)&sPos[row * PK + c8];
        __nv_bfloat16 abuf[8];
#pragma unroll
        for (int j = 0; j < 8; ++j)
            abuf[j] = __float2bfloat16(qp[j] - kp[j] + __bfloat162float(pb[j]));
        *(uint4*)&sR4[row * PK + c8] = *(uint4*)abuf;
    }
    __syncthreads();

    // MMA1: a0 @ gw1 -> h (bf16) into R1 (dw2 img dead)
    ZACC();
    warp_mma_tile(uR4, uR2, wm, wn, lane, acc);
    __syncthreads();   // order: all fragment reads of this phase complete
#pragma unroll
    for (int mt = 0; mt < 2; ++mt) {
#pragma unroll
        for (int nt = 0; nt < 8; ++nt) {
            int R  = wm * 32 + mt * 16 + rq;
            int Cc = wn * 64 + nt * 8 + qc;
            float bx = sb1v[Cc], by = sb1v[Cc + 1];
            __nv_bfloat16 h0[2], h1[2];
            h0[0] = __float2bfloat16(fmaxf(acc[mt][nt][0] + bx, 0.f));
            h0[1] = __float2bfloat16(fmaxf(acc[mt][nt][1] + by, 0.f));
            h1[0] = __float2bfloat16(fmaxf(acc[mt][nt][2] + bx, 0.f));
            h1[1] = __float2bfloat16(fmaxf(acc[mt][nt][3] + by, 0.f));
            *(uint32_t*)&sR1[R * PK + Cc]       = *(uint32_t*)h0;
            *(uint32_t*)&sR1[(R + 8) * PK + Cc] = *(uint32_t*)h1;
        }
    }
    __syncthreads();

    // MMA2: h @ gw2 -> a
    ZACC();
    warp_mma_tile(uR1, uR3, wm, wn, lane, acc);
    __syncthreads();   // all warps done reading R3/R4 before aW overlay

    const float scale = 0.08838834764831845f;  // 1/sqrt(128)
#pragma unroll
    for (int mt = 0; mt < 2; ++mt) {
#pragma unroll
        for (int nt = 0; nt < 8; ++nt) {
            int R  = wm * 32 + mt * 16 + rq;
            int Cc = wn * 64 + nt * 8 + qc;
            float bx = sb2v[Cc], by = sb2v[Cc + 1];
            float2 lo = make_float2((acc[mt][nt][0] + bx) * scale,
                                    (acc[mt][nt][1] + by) * scale);
            float2 hi = make_float2((acc[mt][nt][2] + bx) * scale,
                                    (acc[mt][nt][3] + by) * scale);
            *(float2*)&aW[R * PAW + Cc]       = lo;
            *(float2*)&aW[(R + 8) * PAW + Cc] = hi;
        }
    }
    __syncthreads();

    // softmax over K + aggregate relu(v_gather + pos)
    for (int rep = 0; rep < 4; ++rep) {
        const int pp = rep * 2 + (tid >> 7);   // point 0..7
        const int c  = tid & 127;
        const int r0 = pp * 16;

        float av[K_];
        float mx = -INFINITY;
#pragma unroll
        for (int kk = 0; kk < K_; ++kk) {
            av[kk] = aW[(r0 + kk) * PAW + c];
            mx = fmaxf(mx, av[kk]);
        }
        float s = 0.f;
#pragma unroll
        for (int kk = 0; kk < K_; ++kk) {
            av[kk] = __expf(av[kk] - mx);
            s += av[kk];
        }
        const float inv = 1.f / s;

        float r = 0.f;
#pragma unroll
        for (int kk = 0; kk < K_; ++kk) {
            float vv = p.v[(((long)t << 12) + sidx[r0 + kk]) * 128 + c]
                     + __bfloat162float(sPos[(r0 + kk) * PK + c]);
            r = fmaf(av[kk], fmaxf(vv, 0.f), r);
        }
        p.res[(long)(tp0 + pp) * 128 + c] = __float2bfloat16(r * inv);
    }
#undef ZACC
}

// ---------------------------------------------------------------------------
// x = feats @ fc1_w + fc1_b (transpose of features fused), output bf16.
// ---------------------------------------------------------------------------
__global__ void xproj_kernel(const float* __restrict__ features,
                             const float* __restrict__ W,
                             const float* __restrict__ bias,
                             __nv_bfloat16* __restrict__ X)
{
    float* smf = (float*)dsm;
    float* sAT = smf;                 // [128 d][64 ml]
    float* sB  = smf + 128 * 64;      // [128][128]

    const int tid = threadIdx.x;
    const int t   = blockIdx.y;
    const int bm  = blockIdx.x * 64;

    for (int i = tid * 4; i < 128 * 128; i += 1024)
        *(float4*)&sB[i] = *(const float4*)&W[i];
    for (int i = tid; i < 128 * 64; i += 256) {
        int d  = i >> 6;
        int ml = i & 63;
        sAT[d * 64 + ml] = features[((long)t * D_ + d) * M_ + bm + ml];
    }
    __syncthreads();

    const int cg = tid & 31;
    const int rg = tid >> 5;
    float acc[8][4];
#pragma unroll
    for (int j = 0; j < 8; ++j)
#pragma unroll
        for (int c = 0; c < 4; ++c) acc[j][c] = 0.f;

#pragma unroll 8
    for (int d = 0; d < 128; ++d) {
        float4 b = *(float4*)&sB[d * 128 + cg * 4];
#pragma unroll
        for (int j = 0; j < 8; ++j) {
            float a = sAT[d * 64 + rg * 8 + j];
            acc[j][0] = fmaf(a, b.x, acc[j][0]);
            acc[j][1] = fmaf(a, b.y, acc[j][1]);
            acc[j][2] = fmaf(a, b.z, acc[j][2]);
            acc[j][3] = fmaf(a, b.w, acc[j][3]);
        }
    }

    float4 bb = *(const float4*)&bias[cg * 4];
#pragma unroll
    for (int j = 0; j < 8; ++j) {
        __nv_bfloat16 ob[4];
        ob[0] = __float2bfloat16(acc[j][0] + bb.x);
        ob[1] = __float2bfloat16(acc[j][1] + bb.y);
        ob[2] = __float2bfloat16(acc[j][2] + bb.z);
        ob[3] = __float2bfloat16(acc[j][3] + bb.w);
        *(uint2*)&X[((long)t * M_ + bm + rg * 8 + j) * 128 + cg * 4] = *(uint2*)ob;
    }
}

// ---------------------------------------------------------------------------
// KNN v2: register-resident distances; shfl block argmin; owner-only rescan.
// ---------------------------------------------------------------------------
__global__ void __launch_bounds__(128) knn_kernel(
    const float* __restrict__ xyz,
    const float* __restrict__ mask,
    int* __restrict__ knn)
{
    __shared__ float swv[4];
    __shared__ int   swi[4];
    __shared__ int   sgidx;

    const int t = blockIdx.x >> 12;
    const int m = blockIdx.x & 4095;
    const int tid = threadIdx.x;
    const int lane = tid & 31;
    const int warp = tid >> 5;

    const float* xz = xyz + (long)t * M_ * 3;
    const float x0 = xz[m * 3 + 0];
    const float y0 = xz[m * 3 + 1];
    const float z0 = xz[m * 3 + 2];
    const float mm = mask[(long)t * M_ + m];

    float dl[32];
    float bv = INFINITY;
    int   bi = M_;
#pragma unroll
    for (int ii = 0; ii < 32; ++ii) {
        int j = tid + ii * 128;
        float dx = x0 - xz[j * 3 + 0];
        float dy = y0 - xz[j * 3 + 1];
        float dz = z0 - xz[j * 3 + 2];
        float d  = dx * dx + dy * dy + dz * dz
                 + (1.0f - mm * mask[(long)t * M_ + j]) * 1e6f;
        dl[ii] = d;
        if (d < bv || (d == bv && j < bi)) { bv = d; bi = j; }
    }

    for (int r = 0; r < K_ + 1; ++r) {
        float v = bv; int i = bi;
#pragma unroll
        for (int s = 16; s > 0; s >>= 1) {
            float ov = __shfl_down_sync(0xffffffffu, v, s);
            int   oi = __shfl_down_sync(0xffffffffu, i, s);
            if (ov < v || (ov == v && oi < i)) { v = ov; i = oi; }
        }
        if (lane == 0) { swv[warp] = v; swi[warp] = i; }
        __syncthreads();
        if (tid == 0) {
            float gv = swv[0]; int gi = swi[0];
#pragma unroll
            for (int w = 1; w < 4; ++w) {
                if (swv[w] < gv || (swv[w] == gv && swi[w] < gi)) {
                    gv = swv[w]; gi = swi[w];
                }
            }
            sgidx = gi;
            if (r > 0) knn[(long)blockIdx.x * K_ + (r - 1)] = gi;
        }
        __syncthreads();
        const int win = sgidx;
        if ((win & 127) == tid) {
            const int kill = win >> 7;
#pragma unroll
            for (int ii = 0; ii < 32; ++ii)
                if (ii == kill) dl[ii] = INFINITY;
            bv = INFINITY; bi = M_;
#pragma unroll
            for (int ii = 0; ii < 32; ++ii) {
                int j = tid + ii * 128;
                float d = dl[ii];
                if (d < bv || (d == bv && j < bi)) { bv = d; bi = j; }
            }
        }
        __syncthreads();
    }
}

// ---------------------------------------------------------------------------
// out[t,d,m] = cfc2[t,m,d] + features[t,d,m]
// ---------------------------------------------------------------------------
__global__ void out_kernel(const float* __restrict__ cfc2,
                           const float* __restrict__ features,
                           float* __restrict__ out)
{
    const long i = (long)blockIdx.x * blockDim.x + threadIdx.x;
    if (i >= (long)T_ * D_ * M_) return;
    const int  m  = (int)(i & 4095);
    const long td = i >> 12;
    const int  d  = (int)(td & 127);
    const int  t  = (int)(td >> 7);
    out[i] = cfc2[((long)t * M_ + m) * 128 + d] + features[i];
}

// ---------------------------------------------------------------------------
// Launch
// ---------------------------------------------------------------------------
extern "C" void kernel_launch(void* const* d_in, const int* in_sizes, int n_in,
                              void* d_out, int out_size)
{
    const float* features = (const float*)d_in[0];
    const float* xyz      = (const float*)d_in[1];
    const float* mask     = (const float*)d_in[2];
    const float* fc1_w    = (const float*)d_in[3];
    const float* fc1_b    = (const float*)d_in[4];
    const float* fc2_w    = (const float*)d_in[5];
    const float* fc2_b    = (const float*)d_in[6];
    const float* dw1      = (const float*)d_in[7];
    const float* db1      = (const float*)d_in[8];
    const float* dw2      = (const float*)d_in[9];
    const float* db2      = (const float*)d_in[10];
    const float* gw1      = (const float*)d_in[11];
    const float* gb1      = (const float*)d_in[12];
    const float* gw2      = (const float*)d_in[13];
    const float* gb2      = (const float*)d_in[14];
    const float* wq       = (const float*)d_in[15];
    const float* wk       = (const float*)d_in[16];
    const float* wv       = (const float*)d_in[17];
    float* out = (float*)d_out;

    const int GEMM_SMEM  = 2048 + 2 * TILEB;               // 71680
    const int FUSED_SMEM = 4096 + 5 * TILEB;               // 178176
    const int XPROJ_SMEM = (128 * 64 + 128 * 128) * 4;     // 96KB

    cudaFuncSetAttribute((const void*)mma_gemm,
                         cudaFuncAttributeMaxDynamicSharedMemorySize, GEMM_SMEM);
    cudaFuncSetAttribute((const void*)gamma_soft_mma,
                         cudaFuncAttributeMaxDynamicSharedMemorySize, FUSED_SMEM);
    cudaFuncSetAttribute((const void*)xproj_kernel,
                         cudaFuncAttributeMaxDynamicSharedMemorySize, XPROJ_SMEM);

    float *q, *k, *v, *zero;
    __nv_bfloat16 *xbf, *resb, *wimg;
    int* knn;
    cudaGetSymbolAddress((void**)&xbf,  g_xbf);
    cudaGetSymbolAddress((void**)&q,    g_q);
    cudaGetSymbolAddress((void**)&k,    g_k);
    cudaGetSymbolAddress((void**)&v,    g_v);
    cudaGetSymbolAddress((void**)&resb, g_resb);
    cudaGetSymbolAddress((void**)&knn,  g_knn);
    cudaGetSymbolAddress((void**)&zero, g_zero);
    cudaGetSymbolAddress((void**)&wimg, g_wimg);
    float* fc2o = q;   // q is dead after the fused kernel

    // 0) bf16 W^T images: 0=wq 1=wk 2=wv 3=dw2 4=gw1 5=gw2 6=fc2
    {
        WP wp; wp.w[0] = wq; wp.w[1] = wk; wp.w[2] = wv; wp.w[3] = dw2;
        wp.w[4] = gw1; wp.w[5] = gw2; wp.w[6] = fc2_w;
        prep_weights<<<7, 256>>>(wp, wimg);
    }

    // 1) x = feats @ fc1_w + fc1_b (bf16 out)
    {
        dim3 grid(M_ / 64, T_);
        xproj_kernel<<<grid, 256, XPROJ_SMEM>>>(features, fc1_w, fc1_b, xbf);
    }

    // 2) KNN
    knn_kernel<<<RP, 128>>>(xyz, mask, knn);

    // 3) q, k, v in ONE launch (zero bias)
    {
        MG p{}; p.Abf = xbf; p.bias = zero;
        p.Bimg[0] = wimg;             p.C[0] = q;
        p.Bimg[1] = wimg + 16384;     p.C[1] = k;
        p.Bimg[2] = wimg + 2 * 16384; p.C[2] = v;
        dim3 grid(RP / 128, 3);
        mma_gemm<<<grid, 256, GEMM_SMEM>>>(p);
    }

    // 4) fully fused: pos MLP + gamma MLP + softmax + aggregate -> res
    {
        GF p{};
        p.q = q; p.k = k; p.v = v; p.xyz = xyz; p.knn = knn;
        p.Bpos = wimg + 3 * 16384;
        p.B1img = wimg + 4 * 16384; p.B2img = wimg + 5 * 16384;
        p.dw1 = dw1; p.db1 = db1; p.db2 = db2;
        p.b1 = gb1; p.b2 = gb2; p.res = resb;
        gamma_soft_mma<<<RN / 128, 256, FUSED_SMEM>>>(p);
    }

    // 5) fc2 + residual + transpose
    {
        MG p{}; p.Abf = resb; p.Bimg[0] = wimg + 6 * 16384;
        p.bias = fc2_b; p.C[0] = fc2o;
        mma_gemm<<<dim3(RP / 128, 1), 256, GEMM_SMEM>>>(p);
    }
    {
        long total = (long)T_ * D_ * M_;
        int blocks = (int)((total + 255) / 256);
        out_kernel<<<blocks, 256>>>(fc2o, features, out);
    }
    (void)in_sizes; (void)n_in; (void)out_size;
}

// round 16
// speedup vs baseline: 1.6686x; 1.6686x over previous
#include <cuda_runtime.h>
#include <cuda_bf16.h>
#include <math.h>
#include <stdint.h>

// ---------------------------------------------------------------------------
// Problem constants
// ---------------------------------------------------------------------------
namespace {
constexpr int T_  = 4;
constexpr int N_  = 512;
constexpr int C_  = 8;
constexpr int D_  = 128;
constexpr int DM_ = 128;
constexpr int K_  = 16;
constexpr int M_  = N_ * C_;     // 4096
constexpr int RP  = T_ * M_;     // 16384
constexpr int RN  = RP * K_;     // 262144

constexpr int PK    = 136;             // padded bf16 row stride (272 B)
constexpr int TILEB = 128 * PK * 2;    // 34816 bytes per 128x128 bf16 tile
constexpr int PAW   = 132;             // padded fp32 stride for the 'a' tile
}

extern __shared__ __align__(1024) char dsm[];

// ---------------------------------------------------------------------------
// Scratch (device globals; zero-initialized; no allocation allowed)
// ---------------------------------------------------------------------------
__device__ float          g_zero[128];
__device__ __nv_bfloat16  g_xbf [RP * DM_];
__device__ __nv_bfloat16  g_qb  [RP * DM_];
__device__ __nv_bfloat16  g_kb  [RP * DM_];
__device__ __nv_bfloat16  g_vb  [RP * DM_];
__device__ __nv_bfloat16  g_posb[RN * DM_];
__device__ __nv_bfloat16  g_resb[RP * DM_];
__device__ float          g_fc2o[RP * DM_];
__device__ int            g_knn [RP * K_];
__device__ __nv_bfloat16  g_wimg[7 * 16384];   // bf16 W^T images, [n][k] row-major

// ---------------------------------------------------------------------------
// Warp-level bf16 MMA (baseline PTX; fine on plain sm_103 target).
// Scalar LDS fragment loads (measured faster than ldmatrix here, R15).
// ---------------------------------------------------------------------------
__device__ __forceinline__ void mma16816(float* c, const uint32_t* a,
                                         uint32_t b0, uint32_t b1) {
    asm volatile(
        "mma.sync.aligned.m16n8k16.row.col.f32.bf16.bf16.f32 "
        "{%0,%1,%2,%3}, {%4,%5,%6,%7}, {%8,%9}, {%0,%1,%2,%3};"
        : "+f"(c[0]), "+f"(c[1]), "+f"(c[2]), "+f"(c[3])
        : "r"(a[0]), "r"(a[1]), "r"(a[2]), "r"(a[3]), "r"(b0), "r"(b1));
}

// Warp computes a 32x64 slice of C = A[128xK=128] @ B^T (B stored [n][k]).
// PK=136 padding: bank = (row*68 + word) & 31 -> conflict-free fragments.
__device__ __forceinline__ void warp_mma_tile(
    const __nv_bfloat16* sA, const __nv_bfloat16* sB,
    int wm, int wn, int lane, float acc[2][8][4])
{
    const int rq = lane >> 2;
    const int qc = (lane & 3) * 2;
#pragma unroll
    for (int ks = 0; ks < 8; ++ks) {
        const int k0 = ks * 16;
        uint32_t a[2][4];
#pragma unroll
        for (int mt = 0; mt < 2; ++mt) {
            const __nv_bfloat16* ar = sA + (wm * 32 + mt * 16 + rq) * PK + k0 + qc;
            a[mt][0] = *(const uint32_t*)(ar);
            a[mt][1] = *(const uint32_t*)(ar + 8 * PK);
            a[mt][2] = *(const uint32_t*)(ar + 8);
            a[mt][3] = *(const uint32_t*)(ar + 8 * PK + 8);
        }
#pragma unroll
        for (int nt = 0; nt < 8; ++nt) {
            const __nv_bfloat16* br = sB + (wn * 64 + nt * 8 + rq) * PK + k0 + qc;
            uint32_t b0 = *(const uint32_t*)(br);
            uint32_t b1 = *(const uint32_t*)(br + 8);
            mma16816(acc[0][nt], a[0], b0, b1);
            mma16816(acc[1][nt], a[1], b0, b1);
        }
    }
}

// ---------------------------------------------------------------------------
// Weight prep: img[b][n][k] = bf16(W_b[k][n])
// ---------------------------------------------------------------------------
struct WP { const float* w[7]; };
__global__ void prep_weights(WP p, __nv_bfloat16* img)
{
    const int b = blockIdx.x;
    const float* W = p.w[b];
    __nv_bfloat16* base = img + b * 16384;
    for (int i = threadIdx.x; i < 16384; i += blockDim.x) {
        int n = i >> 7, k = i & 127;
        base[i] = __float2bfloat16(W[k * 128 + n]);
    }
}

// ---------------------------------------------------------------------------
// Tensor-core GEMM: out[128-row tile][128] = A @ W + bias.
// blockIdx.y selects (Bimg, out) pair -> q/k/v in one launch.
// BOUT: bf16 output (q/k/v/pos) or fp32 (fc2).
// smem 2048 + 2*TILEB = 71680 -> 2 CTA/SM.
// ---------------------------------------------------------------------------
enum { ASRC_PLAIN = 0, ASRC_POSH = 1 };
struct MG {
    const __nv_bfloat16* Abf;
    const __nv_bfloat16* Bimg[3];
    void* C[3];
    const float* bias;
    const float* xyz; const int* knn; const float* w1; const float* b1;
};

template <int ASRC, bool BOUT>
__global__ void __launch_bounds__(256, 2) mma_gemm(MG p)
{
    char* smem = dsm;
    float* sbias = (float*)smem;                       // 512 B
    float* srel  = (float*)(smem + 512);               // 1536 B (POSH)
    __nv_bfloat16* sA = (__nv_bfloat16*)(smem + 2048);
    __nv_bfloat16* sB = (__nv_bfloat16*)(smem + 2048 + TILEB);

    const int tid = threadIdx.x;
    const long bm = (long)blockIdx.x * 128;
    const __nv_bfloat16* Bimg = p.Bimg[blockIdx.y];
    void* Cout = p.C[blockIdx.y];

    if (tid < 128) sbias[tid] = p.bias[tid];

    for (int i = tid * 8; i < 128 * 128; i += 256 * 8) {
        int n = i >> 7, c8 = i & 127;
        *(uint4*)&sB[n * PK + c8] = *(const uint4*)&Bimg[i];
    }

    if (ASRC == ASRC_POSH) {
        if (tid < 128) {
            long gr = bm + tid;
            int idx = p.knn[gr];
            int tm  = (int)(gr >> 4);
            int t   = tm >> 12;
            int m   = tm & 4095;
            const float* xz = p.xyz + (long)t * M_ * 3;
            srel[tid * 3 + 0] = xz[m * 3 + 0] - xz[idx * 3 + 0];
            srel[tid * 3 + 1] = xz[m * 3 + 1] - xz[idx * 3 + 1];
            srel[tid * 3 + 2] = xz[m * 3 + 2] - xz[idx * 3 + 2];
        }
        __syncthreads();
        for (int it = 0; it < 8; ++it) {
            int el  = it * 256 + tid;
            int row = el >> 4;
            int c8  = (el & 15) * 8;
            float rx = srel[row * 3 + 0];
            float ry = srel[row * 3 + 1];
            float rz = srel[row * 3 + 2];
            __nv_bfloat16 buf[8];
#pragma unroll
            for (int j = 0; j < 8; ++j) {
                int c = c8 + j;
                float v = fmaf(rx, p.w1[c], fmaf(ry, p.w1[128 + c],
                            fmaf(rz, p.w1[256 + c], p.b1[c])));
                buf[j] = __float2bfloat16(fmaxf(v, 0.f));
            }
            *(uint4*)&sA[row * PK + c8] = *(uint4*)buf;
        }
    } else {
        for (int it = 0; it < 8; ++it) {
            int el  = it * 256 + tid;
            int row = el >> 4;
            int c8  = (el & 15) * 8;
            *(uint4*)&sA[row * PK + c8] = *(const uint4*)&p.Abf[(bm + row) * 128 + c8];
        }
    }
    __syncthreads();

    const int lane = tid & 31;
    const int wm = tid >> 6;
    const int wn = (tid >> 5) & 1;
    float acc[2][8][4];
#pragma unroll
    for (int mt = 0; mt < 2; ++mt)
#pragma unroll
        for (int nt = 0; nt < 8; ++nt)
#pragma unroll
            for (int c = 0; c < 4; ++c) acc[mt][nt][c] = 0.f;

    warp_mma_tile(sA, sB, wm, wn, lane, acc);

    const int rq = lane >> 2;
    const int qc = (lane & 3) * 2;
#pragma unroll
    for (int mt = 0; mt < 2; ++mt) {
#pragma unroll
        for (int nt = 0; nt < 8; ++nt) {
            int R  = wm * 32 + mt * 16 + rq;
            int Cc = wn * 64 + nt * 8 + qc;
            float bx = sbias[Cc], by = sbias[Cc + 1];
            float c0 = acc[mt][nt][0] + bx, c1 = acc[mt][nt][1] + by;
            float c2 = acc[mt][nt][2] + bx, c3 = acc[mt][nt][3] + by;
            if (BOUT) {
                __nv_bfloat16* ob = (__nv_bfloat16*)Cout;
                __nv_bfloat16 lo[2] = {__float2bfloat16(c0), __float2bfloat16(c1)};
                __nv_bfloat16 hi[2] = {__float2bfloat16(c2), __float2bfloat16(c3)};
                *(uint32_t*)&ob[(bm + R) * 128 + Cc]     = *(uint32_t*)lo;
                *(uint32_t*)&ob[(bm + R + 8) * 128 + Cc] = *(uint32_t*)hi;
            } else {
                float* of = (float*)Cout;
                *(float2*)&of[(bm + R) * 128 + Cc]     = make_float2(c0, c1);
                *(float2*)&of[(bm + R + 8) * 128 + Cc] = make_float2(c2, c3);
            }
        }
    }
}

// ---------------------------------------------------------------------------
// Fused gamma MLP + softmax + aggregate (mma.sync), 2 CTA/SM.
// Regions: R1 @2048 = gw1 -> H; R2 @2048+T = gw2; R3 @2048+2T = A(a0).
// aW fp32 [128][132] overlays R2+R3 after MMA2. q/k/v/pos read as bf16.
// smem total = 2048 + 3*TILEB = 106496 -> 2 CTA/SM (16 warps).
// ---------------------------------------------------------------------------
struct GF {
    const __nv_bfloat16* q; const __nv_bfloat16* k; const __nv_bfloat16* v;
    const __nv_bfloat16* pos;
    const int* knn;
    const __nv_bfloat16* B1img; const __nv_bfloat16* B2img;
    const float* b1; const float* b2;
    __nv_bfloat16* res;
};

__global__ void __launch_bounds__(256, 2) gamma_soft_mma(GF p)
{
    char* smem = dsm;
    int*   sidx = (int*)smem;                          // 512 B
    float* sb1v = (float*)(smem + 512);                // 512 B
    float* sb2v = (float*)(smem + 1024);               // 512 B
    __nv_bfloat16* sB1 = (__nv_bfloat16*)(smem + 2048);            // R1 (-> H)
    __nv_bfloat16* sB2 = (__nv_bfloat16*)(smem + 2048 + TILEB);    // R2
    __nv_bfloat16* sA  = (__nv_bfloat16*)(smem + 2048 + 2 * TILEB);// R3
    __nv_bfloat16* sH  = sB1;                                       // reuse R1
    float* aW = (float*)(smem + 2048 + TILEB);         // overlays R2+R3 (67584B)

    const int tid = threadIdx.x;
    const long bm = (long)blockIdx.x * 128;    // neighbor-row base
    const int tp0 = blockIdx.x * 8;            // first point
    const int t   = tp0 >> 12;

    if (tid < 128) {
        sidx[tid] = p.knn[bm + tid];
        sb1v[tid] = p.b1[tid];
        sb2v[tid] = p.b2[tid];
    }
    for (int i = tid * 8; i < 128 * 128; i += 256 * 8) {
        int n = i >> 7, c8 = i & 127;
        *(uint4*)&sB1[n * PK + c8] = *(const uint4*)&p.B1img[i];
        *(uint4*)&sB2[n * PK + c8] = *(const uint4*)&p.B2img[i];
    }
    __syncthreads();

    // build a0 = q - k_gather + pos (all bf16 in gmem; fp32 math)
    for (int it = 0; it < 8; ++it) {
        int el  = it * 256 + tid;
        int row = el >> 4;
        int c8  = (el & 15) * 8;
        int tm  = tp0 + (row >> 4);
        __nv_bfloat16 qb[8], kb[8], pb[8], abuf[8];
        *(uint4*)qb = *(const uint4*)&p.q[(long)tm * 128 + c8];
        *(uint4*)kb = *(const uint4*)&p.k[(((long)t << 12) + sidx[row]) * 128 + c8];
        *(uint4*)pb = *(const uint4*)&p.pos[(bm + row) * 128 + c8];
#pragma unroll
        for (int j = 0; j < 8; ++j)
            abuf[j] = __float2bfloat16(__bfloat162float(qb[j])
                                     - __bfloat162float(kb[j])
                                     + __bfloat162float(pb[j]));
        *(uint4*)&sA[row * PK + c8] = *(uint4*)abuf;
    }
    __syncthreads();

    const int lane = tid & 31;
    const int wm = tid >> 6;
    const int wn = (tid >> 5) & 1;
    const int rq = lane >> 2;
    const int qc = (lane & 3) * 2;

    // MMA1: a0 @ B1
    float acc[2][8][4];
#pragma unroll
    for (int mt = 0; mt < 2; ++mt)
#pragma unroll
        for (int nt = 0; nt < 8; ++nt)
#pragma unroll
            for (int c = 0; c < 4; ++c) acc[mt][nt][c] = 0.f;
    warp_mma_tile(sA, sB1, wm, wn, lane, acc);
    __syncthreads();   // all warps done reading B1 before H overwrites it

    // h = relu(acc + b1) -> bf16 padded into R1 (was B1)
#pragma unroll
    for (int mt = 0; mt < 2; ++mt) {
#pragma unroll
        for (int nt = 0; nt < 8; ++nt) {
            int R  = wm * 32 + mt * 16 + rq;
            int Cc = wn * 64 + nt * 8 + qc;
            float bx = sb1v[Cc], by = sb1v[Cc + 1];
            __nv_bfloat16 h0[2], h1[2];
            h0[0] = __float2bfloat16(fmaxf(acc[mt][nt][0] + bx, 0.f));
            h0[1] = __float2bfloat16(fmaxf(acc[mt][nt][1] + by, 0.f));
            h1[0] = __float2bfloat16(fmaxf(acc[mt][nt][2] + bx, 0.f));
            h1[1] = __float2bfloat16(fmaxf(acc[mt][nt][3] + by, 0.f));
            *(uint32_t*)&sH[R * PK + Cc]       = *(uint32_t*)h0;
            *(uint32_t*)&sH[(R + 8) * PK + Cc] = *(uint32_t*)h1;
        }
    }
    __syncthreads();

    // MMA2: h @ B2 -> a
#pragma unroll
    for (int mt = 0; mt < 2; ++mt)
#pragma unroll
        for (int nt = 0; nt < 8; ++nt)
#pragma unroll
            for (int c = 0; c < 4; ++c) acc[mt][nt][c] = 0.f;
    warp_mma_tile(sH, sB2, wm, wn, lane, acc);

    __syncthreads();   // all warps done reading sA/B2 before aW overlay

    const float scale = 0.08838834764831845f;  // 1/sqrt(128)
#pragma unroll
    for (int mt = 0; mt < 2; ++mt) {
#pragma unroll
        for (int nt = 0; nt < 8; ++nt) {
            int R  = wm * 32 + mt * 16 + rq;
            int Cc = wn * 64 + nt * 8 + qc;
            float bx = sb2v[Cc], by = sb2v[Cc + 1];
            float2 lo = make_float2((acc[mt][nt][0] + bx) * scale,
                                    (acc[mt][nt][1] + by) * scale);
            float2 hi = make_float2((acc[mt][nt][2] + bx) * scale,
                                    (acc[mt][nt][3] + by) * scale);
            *(float2*)&aW[R * PAW + Cc]       = lo;
            *(float2*)&aW[(R + 8) * PAW + Cc] = hi;
        }
    }
    __syncthreads();

    // softmax over K + aggregate relu(v_gather + pos)  (v/pos bf16 gmem)
    for (int rep = 0; rep < 4; ++rep) {
        const int pp = rep * 2 + (tid >> 7);   // point 0..7
        const int c  = tid & 127;
        const int r0 = pp * 16;

        float av[K_];
        float mx = -INFINITY;
#pragma unroll
        for (int kk = 0; kk < K_; ++kk) {
            av[kk] = aW[(r0 + kk) * PAW + c];
            mx = fmaxf(mx, av[kk]);
        }
        float s = 0.f;
#pragma unroll
        for (int kk = 0; kk < K_; ++kk) {
            av[kk] = __expf(av[kk] - mx);
            s += av[kk];
        }
        const float inv = 1.f / s;

        float r = 0.f;
#pragma unroll
        for (int kk = 0; kk < K_; ++kk) {
            float vv = __bfloat162float(
                           p.v[(((long)t << 12) + sidx[r0 + kk]) * 128 + c])
                     + __bfloat162float(p.pos[(bm + r0 + kk) * 128 + c]);
            r = fmaf(av[kk], fmaxf(vv, 0.f), r);
        }
        p.res[(long)(tp0 + pp) * 128 + c] = __float2bfloat16(r * inv);
    }
}

// ---------------------------------------------------------------------------
// x = feats @ fc1_w + fc1_b (transpose of features fused), output bf16.
// ---------------------------------------------------------------------------
__global__ void xproj_kernel(const float* __restrict__ features,
                             const float* __restrict__ W,
                             const float* __restrict__ bias,
                             __nv_bfloat16* __restrict__ X)
{
    float* smf = (float*)dsm;
    float* sAT = smf;                 // [128 d][64 ml]
    float* sB  = smf + 128 * 64;      // [128][128]

    const int tid = threadIdx.x;
    const int t   = blockIdx.y;
    const int bm  = blockIdx.x * 64;

    for (int i = tid * 4; i < 128 * 128; i += 1024)
        *(float4*)&sB[i] = *(const float4*)&W[i];
    for (int i = tid; i < 128 * 64; i += 256) {
        int d  = i >> 6;
        int ml = i & 63;
        sAT[d * 64 + ml] = features[((long)t * D_ + d) * M_ + bm + ml];
    }
    __syncthreads();

    const int cg = tid & 31;
    const int rg = tid >> 5;
    float acc[8][4];
#pragma unroll
    for (int j = 0; j < 8; ++j)
#pragma unroll
        for (int c = 0; c < 4; ++c) acc[j][c] = 0.f;

#pragma unroll 8
    for (int d = 0; d < 128; ++d) {
        float4 b = *(float4*)&sB[d * 128 + cg * 4];
#pragma unroll
        for (int j = 0; j < 8; ++j) {
            float a = sAT[d * 64 + rg * 8 + j];
            acc[j][0] = fmaf(a, b.x, acc[j][0]);
            acc[j][1] = fmaf(a, b.y, acc[j][1]);
            acc[j][2] = fmaf(a, b.z, acc[j][2]);
            acc[j][3] = fmaf(a, b.w, acc[j][3]);
        }
    }

    float4 bb = *(const float4*)&bias[cg * 4];
#pragma unroll
    for (int j = 0; j < 8; ++j) {
        __nv_bfloat16 ob[4];
        ob[0] = __float2bfloat16(acc[j][0] + bb.x);
        ob[1] = __float2bfloat16(acc[j][1] + bb.y);
        ob[2] = __float2bfloat16(acc[j][2] + bb.z);
        ob[3] = __float2bfloat16(acc[j][3] + bb.w);
        *(uint2*)&X[((long)t * M_ + bm + rg * 8 + j) * 128 + cg * 4] = *(uint2*)ob;
    }
}

// ---------------------------------------------------------------------------
// KNN v2: register-resident distances; shfl block argmin; owner-only rescan.
// Stable (d, j) lexicographic selection == jnp.argsort stable order.
// ---------------------------------------------------------------------------
__global__ void __launch_bounds__(128) knn_kernel(
    const float* __restrict__ xyz,
    const float* __restrict__ mask,
    int* __restrict__ knn)
{
    __shared__ float swv[4];
    __shared__ int   swi[4];
    __shared__ int   sgidx;

    const int t = blockIdx.x >> 12;
    const int m = blockIdx.x & 4095;
    const int tid = threadIdx.x;
    const int lane = tid & 31;
    const int warp = tid >> 5;

    const float* xz = xyz + (long)t * M_ * 3;
    const float x0 = xz[m * 3 + 0];
    const float y0 = xz[m * 3 + 1];
    const float z0 = xz[m * 3 + 2];
    const float mm = mask[(long)t * M_ + m];

    float dl[32];
    float bv = INFINITY;
    int   bi = M_;
#pragma unroll
    for (int ii = 0; ii < 32; ++ii) {
        int j = tid + ii * 128;
        float dx = x0 - xz[j * 3 + 0];
        float dy = y0 - xz[j * 3 + 1];
        float dz = z0 - xz[j * 3 + 2];
        float d  = dx * dx + dy * dy + dz * dz
                 + (1.0f - mm * mask[(long)t * M_ + j]) * 1e6f;
        dl[ii] = d;
        if (d < bv || (d == bv && j < bi)) { bv = d; bi = j; }
    }

    for (int r = 0; r < K_ + 1; ++r) {
        float v = bv; int i = bi;
#pragma unroll
        for (int s = 16; s > 0; s >>= 1) {
            float ov = __shfl_down_sync(0xffffffffu, v, s);
            int   oi = __shfl_down_sync(0xffffffffu, i, s);
            if (ov < v || (ov == v && oi < i)) { v = ov; i = oi; }
        }
        if (lane == 0) { swv[warp] = v; swi[warp] = i; }
        __syncthreads();
        if (tid == 0) {
            float gv = swv[0]; int gi = swi[0];
#pragma unroll
            for (int w = 1; w < 4; ++w) {
                if (swv[w] < gv || (swv[w] == gv && swi[w] < gi)) {
                    gv = swv[w]; gi = swi[w];
                }
            }
            sgidx = gi;
            if (r > 0) knn[(long)blockIdx.x * K_ + (r - 1)] = gi;
        }
        __syncthreads();
        const int win = sgidx;
        if ((win & 127) == tid) {
            const int kill = win >> 7;
#pragma unroll
            for (int ii = 0; ii < 32; ++ii)
                if (ii == kill) dl[ii] = INFINITY;
            bv = INFINITY; bi = M_;
#pragma unroll
            for (int ii = 0; ii < 32; ++ii) {
                int j = tid + ii * 128;
                float d = dl[ii];
                if (d < bv || (d == bv && j < bi)) { bv = d; bi = j; }
            }
        }
        __syncthreads();
    }
}

// ---------------------------------------------------------------------------
// out[t,d,m] = cfc2[t,m,d] + features[t,d,m]
// ---------------------------------------------------------------------------
__global__ void out_kernel(const float* __restrict__ cfc2,
                           const float* __restrict__ features,
                           float* __restrict__ out)
{
    const long i = (long)blockIdx.x * blockDim.x + threadIdx.x;
    if (i >= (long)T_ * D_ * M_) return;
    const int  m  = (int)(i & 4095);
    const long td = i >> 12;
    const int  d  = (int)(td & 127);
    const int  t  = (int)(td >> 7);
    out[i] = cfc2[((long)t * M_ + m) * 128 + d] + features[i];
}

// ---------------------------------------------------------------------------
// Launch
// ---------------------------------------------------------------------------
extern "C" void kernel_launch(void* const* d_in, const int* in_sizes, int n_in,
                              void* d_out, int out_size)
{
    const float* features = (const float*)d_in[0];
    const float* xyz      = (const float*)d_in[1];
    const float* mask     = (const float*)d_in[2];
    const float* fc1_w    = (const float*)d_in[3];
    const float* fc1_b    = (const float*)d_in[4];
    const float* fc2_w    = (const float*)d_in[5];
    const float* fc2_b    = (const float*)d_in[6];
    const float* dw1      = (const float*)d_in[7];
    const float* db1      = (const float*)d_in[8];
    const float* dw2      = (const float*)d_in[9];
    const float* db2      = (const float*)d_in[10];
    const float* gw1      = (const float*)d_in[11];
    const float* gb1      = (const float*)d_in[12];
    const float* gw2      = (const float*)d_in[13];
    const float* gb2      = (const float*)d_in[14];
    const float* wq       = (const float*)d_in[15];
    const float* wk       = (const float*)d_in[16];
    const float* wv       = (const float*)d_in[17];
    float* out = (float*)d_out;

    const int GEMM_SMEM  = 2048 + 2 * TILEB;               // 71680
    const int FUSED_SMEM = 2048 + 3 * TILEB;               // 106496
    const int XPROJ_SMEM = (128 * 64 + 128 * 128) * 4;     // 96KB

    cudaFuncSetAttribute((const void*)mma_gemm<ASRC_PLAIN, true>,
                         cudaFuncAttributeMaxDynamicSharedMemorySize, GEMM_SMEM);
    cudaFuncSetAttribute((const void*)mma_gemm<ASRC_PLAIN, false>,
                         cudaFuncAttributeMaxDynamicSharedMemorySize, GEMM_SMEM);
    cudaFuncSetAttribute((const void*)mma_gemm<ASRC_POSH, true>,
                         cudaFuncAttributeMaxDynamicSharedMemorySize, GEMM_SMEM);
    cudaFuncSetAttribute((const void*)gamma_soft_mma,
                         cudaFuncAttributeMaxDynamicSharedMemorySize, FUSED_SMEM);
    cudaFuncSetAttribute((const void*)xproj_kernel,
                         cudaFuncAttributeMaxDynamicSharedMemorySize, XPROJ_SMEM);

    float *zero, *fc2o;
    __nv_bfloat16 *xbf, *qb, *kb, *vb, *posb, *resb, *wimg;
    int* knn;
    cudaGetSymbolAddress((void**)&xbf,  g_xbf);
    cudaGetSymbolAddress((void**)&qb,   g_qb);
    cudaGetSymbolAddress((void**)&kb,   g_kb);
    cudaGetSymbolAddress((void**)&vb,   g_vb);
    cudaGetSymbolAddress((void**)&posb, g_posb);
    cudaGetSymbolAddress((void**)&resb, g_resb);
    cudaGetSymbolAddress((void**)&fc2o, g_fc2o);
    cudaGetSymbolAddress((void**)&knn,  g_knn);
    cudaGetSymbolAddress((void**)&zero, g_zero);
    cudaGetSymbolAddress((void**)&wimg, g_wimg);

    // 0) bf16 W^T images: 0=wq 1=wk 2=wv 3=dw2 4=gw1 5=gw2 6=fc2
    {
        WP wp; wp.w[0] = wq; wp.w[1] = wk; wp.w[2] = wv; wp.w[3] = dw2;
        wp.w[4] = gw1; wp.w[5] = gw2; wp.w[6] = fc2_w;
        prep_weights<<<7, 256>>>(wp, wimg);
    }

    // 1) x = feats @ fc1_w + fc1_b (bf16 out)
    {
        dim3 grid(M_ / 64, T_);
        xproj_kernel<<<grid, 256, XPROJ_SMEM>>>(features, fc1_w, fc1_b, xbf);
    }

    // 2) KNN
    knn_kernel<<<RP, 128>>>(xyz, mask, knn);

    // 3) q, k, v in ONE launch (zero bias; bf16 out)
    {
        MG p{}; p.Abf = xbf; p.bias = zero;
        p.Bimg[0] = wimg;             p.C[0] = qb;
        p.Bimg[1] = wimg + 16384;     p.C[1] = kb;
        p.Bimg[2] = wimg + 2 * 16384; p.C[2] = vb;
        dim3 grid(RP / 128, 3);
        mma_gemm<ASRC_PLAIN, true><<<grid, 256, GEMM_SMEM>>>(p);
    }

    // 4) pos = relu(rel @ dw1 + db1) @ dw2 + db2  (bf16 out)
    {
        MG p{}; p.Bimg[0] = wimg + 3 * 16384; p.bias = db2; p.C[0] = posb;
        p.xyz = xyz; p.knn = knn; p.w1 = dw1; p.b1 = db1;
        mma_gemm<ASRC_POSH, true><<<dim3(RN / 128, 1), 256, GEMM_SMEM>>>(p);
    }

    // 5) fused gamma MLP + softmax + aggregate -> res (bf16)
    {
        GF p{};
        p.q = qb; p.k = kb; p.v = vb; p.pos = posb; p.knn = knn;
        p.B1img = wimg + 4 * 16384; p.B2img = wimg + 5 * 16384;
        p.b1 = gb1; p.b2 = gb2; p.res = resb;
        gamma_soft_mma<<<RN / 128, 256, FUSED_SMEM>>>(p);
    }

    // 6) fc2 + residual + transpose (fp32 out)
    {
        MG p{}; p.Abf = resb; p.Bimg[0] = wimg + 6 * 16384;
        p.bias = fc2_b; p.C[0] = fc2o;
        mma_gemm<ASRC_PLAIN, false><<<dim3(RP / 128, 1), 256, GEMM_SMEM>>>(p);
    }
    {
        long total = (long)T_ * D_ * M_;
        int blocks = (int)((total + 255) / 256);
        out_kernel<<<blocks, 256>>>(fc2o, features, out);
    }
    (void)in_sizes; (void)n_in; (void)out_size;
}